// round 1
// baseline (speedup 1.0000x reference)
#include <cuda_runtime.h>
#include <cuda_bf16.h>
#include <cstdint>

// Problem constants (from reference)
#define H_IMG 240
#define W_IMG 135
#define NPIX  (H_IMG * W_IMG)   // 32400
#define NV    600
#define NF    1000
#define SIGMA_F 1e-4f
#define BLUR_F  9.210240366975850e-4f   // log(1/1e-4 - 1) * 1e-4
#define F_LEN_F 1000.0f
#define C_PP_F  512.0f
#define CAM_F   1024.0f

// Per-face packed data: ax,ay,bx,by,cx,cy,tz,pad  (8 floats = 2 float4)
__device__ float4 g_face[NF * 2];

__global__ void face_pre_kernel(const float* __restrict__ verts,
                                const int*   __restrict__ faces) {
    int f = blockIdx.x * blockDim.x + threadIdx.x;
    if (f >= NF) return;

    float c[6];
    float tz = 0.0f;
#pragma unroll
    for (int k = 0; k < 3; k++) {
        int vi = faces[f * 3 + k];
        float x = verts[vi * 3 + 0];
        float y = verts[vi * 3 + 1];
        float z = verts[vi * 3 + 2];
        // v = verts @ R.T with R = diag(-1,-1,1)
        float vx = -x, vy = -y, vz = z;
        tz += vz;
        float zc = fmaxf(vz, 1e-6f);
        float px = (F_LEN_F * vx / zc + C_PP_F) / CAM_F * (float)W_IMG;
        float py = (F_LEN_F * vy / zc + C_PP_F) / CAM_F * (float)H_IMG;
        c[2 * k + 0] = px;
        c[2 * k + 1] = py;
    }
    tz = tz / 3.0f;
    g_face[f * 2 + 0] = make_float4(c[0], c[1], c[2], c[3]);
    g_face[f * 2 + 1] = make_float4(c[4], c[5], tz, 0.0f);
}

__device__ __forceinline__ void edge_step(float ax, float ay, float bx, float by,
                                          float px, float py,
                                          float& d2min, bool& pos, bool& neg) {
    float abx = bx - ax;
    float aby = by - ay;
    float apx = px - ax;
    float apy = py - ay;
    float cross = abx * apy - aby * apx;
    pos = pos && (cross >= 0.0f);
    neg = neg && (cross <= 0.0f);
    float dd = abx * abx + aby * aby + 1e-12f;
    float t = (apx * abx + apy * aby) / dd;
    t = fminf(fmaxf(t, 0.0f), 1.0f);
    float ex = apx - t * abx;
    float ey = apy - t * aby;
    float d2 = ex * ex + ey * ey;
    d2min = fminf(d2min, d2);
}

__global__ void __launch_bounds__(128)
sil_kernel(float* __restrict__ out) {
    __shared__ float4 sf[NF * 2];   // 32 KB
    for (int i = threadIdx.x; i < NF * 2; i += blockDim.x)
        sf[i] = g_face[i];
    __syncthreads();

    int pix = blockIdx.x * blockDim.x + threadIdx.x;
    if (pix >= NPIX) return;

    int yi = pix / W_IMG;
    int xi = pix - yi * W_IMG;
    float px = (float)xi + 0.5f;
    float py = (float)yi + 0.5f;

    float acc = 0.0f;   // sum of log1p(-prob)

#pragma unroll 2
    for (int f = 0; f < NF; f++) {
        float4 f0 = sf[2 * f + 0];
        float4 f1 = sf[2 * f + 1];
        float ax = f0.x, ay = f0.y;
        float bx = f0.z, by = f0.w;
        float cx = f1.x, cy = f1.y;
        float tz = f1.z;

        float d2min = __int_as_float(0x7f800000);  // +inf
        bool pos = true, neg = true;
        edge_step(ax, ay, bx, by, px, py, d2min, pos, neg);
        edge_step(bx, by, cx, cy, px, py, d2min, pos, neg);
        edge_step(cx, cy, ax, ay, px, py, d2min, pos, neg);

        bool inside = pos || neg;
        bool valid = (tz > 1e-6f) && (inside || (d2min <= BLUR_F));
        if (valid) {
            float sd2 = inside ? -d2min : d2min;
            float xarg = -sd2 / SIGMA_F;
            float prob = 1.0f / (1.0f + expf(-xarg));
            acc += log1pf(-prob);
        }
    }

    float alpha = 1.0f - expf(acc);
    out[1 + pix] = alpha;
}

__global__ void __launch_bounds__(256)
loss_kernel(const float* __restrict__ gt, float* __restrict__ out) {
    __shared__ float red[256];
    int tid = threadIdx.x;
    float s = 0.0f;
    for (int i = tid; i < NPIX; i += 256)
        s += fabsf(out[1 + i] - gt[i]);
    red[tid] = s;
    __syncthreads();
#pragma unroll
    for (int off = 128; off > 0; off >>= 1) {
        if (tid < off) red[tid] += red[tid + off];
        __syncthreads();
    }
    if (tid == 0) out[0] = red[0] / (float)NPIX;
}

extern "C" void kernel_launch(void* const* d_in, const int* in_sizes, int n_in,
                              void* d_out, int out_size) {
    const float* verts = (const float*)d_in[0];
    const float* gt    = (const float*)d_in[1];
    const int*   faces = (const int*)d_in[2];
    float* out = (float*)d_out;

    face_pre_kernel<<<(NF + 255) / 256, 256>>>(verts, faces);
    sil_kernel<<<(NPIX + 127) / 128, 128>>>(out);
    loss_kernel<<<1, 256>>>(gt, out);
}

// round 3
// speedup vs baseline: 5.3079x; 5.3079x over previous
#include <cuda_runtime.h>
#include <cuda_bf16.h>
#include <cstdint>

// Problem constants (from reference)
#define H_IMG 240
#define W_IMG 135
#define NPIX  (H_IMG * W_IMG)   // 32400
#define NV    600
#define NF    1000
#define SIGMA_F 1e-4f
#define BLUR_F  9.210240366975850e-4f   // log(1/1e-4 - 1) * 1e-4
#define MARGIN_F 0.032f                 // > sqrt(BLUR_F) = 0.030348
#define F_LEN_F 1000.0f
#define C_PP_F  512.0f
#define CAM_F   1024.0f

#define TILE_W 16
#define TILE_H 16
#define TILES_X 9    // ceil(135/16)
#define TILES_Y 15   // ceil(240/16)
#define NGROUP 5
#define FACES_PER_G (NF / NGROUP)   // 200
#define NCOMB ((NPIX + 255) / 256)  // 127 combine blocks

// Precomputed per-face edge data (SoA of float4):
//  eA[f] = (a0x, a0y, ab0x, ab0y)
//  eB[f] = (a1x, a1y, ab1x, ab1y)
//  eC[f] = (a2x, a2y, ab2x, ab2y)
//  eD[f] = (inv_dd0, inv_dd1, inv_dd2, unused)
//  bb[f] = (xmin-m, ymin-m, xmax+m, ymax+m)   (empty if tz <= 1e-6)
__device__ float4 g_eA[NF];
__device__ float4 g_eB[NF];
__device__ float4 g_eC[NF];
__device__ float4 g_eD[NF];
__device__ float4 g_bb[NF];

__device__ float g_acc[NGROUP * NPIX];   // partial log-accumulators
__device__ float g_part[NCOMB];          // partial loss sums

__global__ void face_pre_kernel(const float* __restrict__ verts,
                                const int*   __restrict__ faces) {
    int f = blockIdx.x * blockDim.x + threadIdx.x;
    if (f >= NF) return;

    float px[3], py[3];
    float tz = 0.0f;
#pragma unroll
    for (int k = 0; k < 3; k++) {
        int vi = faces[f * 3 + k];
        float x = verts[vi * 3 + 0];
        float y = verts[vi * 3 + 1];
        float z = verts[vi * 3 + 2];
        float vx = -x, vy = -y, vz = z;        // R = diag(-1,-1,1)
        tz += vz;
        float zc = fmaxf(vz, 1e-6f);
        px[k] = (F_LEN_F * vx / zc + C_PP_F) / CAM_F * (float)W_IMG;
        py[k] = (F_LEN_F * vy / zc + C_PP_F) / CAM_F * (float)H_IMG;
    }
    tz *= (1.0f / 3.0f);

    float inv[3];
#pragma unroll
    for (int k = 0; k < 3; k++) {
        int k2 = (k + 1) % 3;
        float abx = px[k2] - px[k];
        float aby = py[k2] - py[k];
        inv[k] = 1.0f / (abx * abx + aby * aby + 1e-12f);
    }

    g_eA[f] = make_float4(px[0], py[0], px[1] - px[0], py[1] - py[0]);
    g_eB[f] = make_float4(px[1], py[1], px[2] - px[1], py[2] - py[1]);
    g_eC[f] = make_float4(px[2], py[2], px[0] - px[2], py[0] - py[2]);
    g_eD[f] = make_float4(inv[0], inv[1], inv[2], tz);

    if (tz > 1e-6f) {
        float xmn = fminf(px[0], fminf(px[1], px[2])) - MARGIN_F;
        float xmx = fmaxf(px[0], fmaxf(px[1], px[2])) + MARGIN_F;
        float ymn = fminf(py[0], fminf(py[1], py[2])) - MARGIN_F;
        float ymx = fmaxf(py[0], fmaxf(py[1], py[2])) + MARGIN_F;
        g_bb[f] = make_float4(xmn, ymn, xmx, ymx);
    } else {
        g_bb[f] = make_float4(1e30f, 1e30f, -1e30f, -1e30f);  // empty
    }
}

__device__ __forceinline__ void edge_step2(float ax, float ay, float abx, float aby,
                                           float invdd, float px, float py,
                                           float& d2min, bool& pos, bool& neg) {
    float apx = px - ax;
    float apy = py - ay;
    float cross = abx * apy - aby * apx;
    pos = pos && (cross >= 0.0f);
    neg = neg && (cross <= 0.0f);
    float t = (apx * abx + apy * aby) * invdd;
    t = fminf(fmaxf(t, 0.0f), 1.0f);
    float ex = apx - t * abx;
    float ey = apy - t * aby;
    float d2 = ex * ex + ey * ey;
    d2min = fminf(d2min, d2);
}

// grid: (TILES_X, TILES_Y, NGROUP), block: (16,16)
__global__ void __launch_bounds__(256)
sil_partial_kernel() {
    __shared__ int   s_idx[FACES_PER_G];
    __shared__ int   s_wcnt[8];
    __shared__ int   s_n;

    int tid  = threadIdx.y * 16 + threadIdx.x;
    int wid  = tid >> 5;
    int lane = tid & 31;

    int gx = blockIdx.x * TILE_W;
    int gy = blockIdx.y * TILE_H;
    int grp = blockIdx.z;

    // tile pixel-center bounds
    float tx0 = (float)gx + 0.5f;
    float tx1 = (float)gx + (float)(TILE_W - 1) + 0.5f;
    float ty0 = (float)gy + 0.5f;
    float ty1 = (float)gy + (float)(TILE_H - 1) + 0.5f;

    // ---- deterministic ordered compaction of this group's faces ----
    int f = grp * FACES_PER_G + tid;
    bool pass = false;
    if (tid < FACES_PER_G) {
        float4 bb = g_bb[f];
        pass = (bb.x <= tx1) && (bb.z >= tx0) && (bb.y <= ty1) && (bb.w >= ty0);
    }
    unsigned mask = __ballot_sync(0xffffffffu, pass);
    if (lane == 0) s_wcnt[wid] = __popc(mask);
    __syncthreads();
    int woff = 0;
#pragma unroll
    for (int w = 0; w < 8; w++) {
        if (w < wid) woff += s_wcnt[w];
    }
    if (pass) {
        int pos = woff + __popc(mask & ((1u << lane) - 1u));
        s_idx[pos] = f;
    }
    if (tid == 0) {
        int tot = 0;
#pragma unroll
        for (int w = 0; w < 8; w++) tot += s_wcnt[w];
        s_n = tot;
    }
    __syncthreads();
    int nf = s_n;

    // ---- per-pixel loop over compacted faces ----
    int xi = gx + threadIdx.x;
    int yi = gy + threadIdx.y;
    float px = (float)xi + 0.5f;
    float py = (float)yi + 0.5f;

    float acc = 0.0f;

    for (int i = 0; i < nf; i++) {
        int fi = s_idx[i];
        float4 eA = __ldg(&g_eA[fi]);
        float4 eB = __ldg(&g_eB[fi]);
        float4 eC = __ldg(&g_eC[fi]);
        float4 eD = __ldg(&g_eD[fi]);

        float d2min = __int_as_float(0x7f800000);  // +inf
        bool pos = true, neg = true;
        edge_step2(eA.x, eA.y, eA.z, eA.w, eD.x, px, py, d2min, pos, neg);
        edge_step2(eB.x, eB.y, eB.z, eB.w, eD.y, px, py, d2min, pos, neg);
        edge_step2(eC.x, eC.y, eC.z, eC.w, eD.z, px, py, d2min, pos, neg);

        bool inside = pos || neg;
        bool valid = inside || (d2min <= BLUR_F);
        if (valid) {
            // x = -signed_d2/sigma ; signed_d2 = inside ? -d2min : d2min
            float xarg = (inside ? d2min : -d2min) * (1.0f / SIGMA_F);
            // log1p(-sigmoid(x)) = -log1p(exp(x))  (softplus)
            acc -= log1pf(__expf(xarg));
        }
    }

    if (xi < W_IMG && yi < H_IMG) {
        int pix = yi * W_IMG + xi;
        g_acc[grp * NPIX + pix] = acc;
    }
}

// grid: NCOMB blocks x 256 — combine groups, write sil, partial loss
__global__ void __launch_bounds__(256)
combine_kernel(const float* __restrict__ gt, float* __restrict__ out) {
    __shared__ float red[256];
    int tid = threadIdx.x;
    int pix = blockIdx.x * 256 + tid;

    float diff = 0.0f;
    if (pix < NPIX) {
        float acc = 0.0f;
#pragma unroll
        for (int g = 0; g < NGROUP; g++)
            acc += g_acc[g * NPIX + pix];
        float alpha = 1.0f - __expf(acc);
        out[1 + pix] = alpha;
        diff = fabsf(alpha - gt[pix]);
    }
    red[tid] = diff;
    __syncthreads();
#pragma unroll
    for (int off = 128; off > 0; off >>= 1) {
        if (tid < off) red[tid] += red[tid + off];
        __syncthreads();
    }
    if (tid == 0) g_part[blockIdx.x] = red[0];
}

__global__ void __launch_bounds__(128)
final_loss_kernel(float* __restrict__ out) {
    __shared__ float red[128];
    int tid = threadIdx.x;
    float s = (tid < NCOMB) ? g_part[tid] : 0.0f;
    red[tid] = s;
    __syncthreads();
#pragma unroll
    for (int off = 64; off > 0; off >>= 1) {
        if (tid < off) red[tid] += red[tid + off];
        __syncthreads();
    }
    if (tid == 0) out[0] = red[0] * (1.0f / (float)NPIX);
}

extern "C" void kernel_launch(void* const* d_in, const int* in_sizes, int n_in,
                              void* d_out, int out_size) {
    const float* verts = (const float*)d_in[0];
    const float* gt    = (const float*)d_in[1];
    const int*   faces = (const int*)d_in[2];
    float* out = (float*)d_out;

    face_pre_kernel<<<(NF + 255) / 256, 256>>>(verts, faces);

    dim3 grid(TILES_X, TILES_Y, NGROUP);
    dim3 block(16, 16);
    sil_partial_kernel<<<grid, block>>>();

    combine_kernel<<<NCOMB, 256>>>(gt, out);
    final_loss_kernel<<<1, 128>>>(out);
}

// round 4
// speedup vs baseline: 9.2640x; 1.7453x over previous
#include <cuda_runtime.h>
#include <cuda_bf16.h>
#include <cstdint>

// Problem constants (from reference)
#define H_IMG 240
#define W_IMG 135
#define NPIX  (H_IMG * W_IMG)   // 32400
#define NV    600
#define NF    1000
#define SIGMA_F 1e-4f
#define BLUR_F  9.210240366975850e-4f   // log(1/1e-4 - 1) * 1e-4
#define MARGIN_F 0.032f                 // > sqrt(BLUR_F) = 0.030348
#define F_LEN_F 1000.0f
#define C_PP_F  512.0f
#define CAM_F   1024.0f

#define TILE_W 16
#define TILE_H 16
#define TILES_X 9     // ceil(135/16)
#define TILES_Y 15    // 240/16
#define NTILES  (TILES_X * TILES_Y)   // 135
#define NGROUP  10
#define FACES_PER_G (NF / NGROUP)     // 100
#define TPB 256

// Cross-CTA communication (device globals; zero-init at load, reset by kernel)
__device__ float g_acc[NTILES * NGROUP * TPB];  // per (tile, group, thread) partial
__device__ float g_tilepart[NTILES];            // per-tile |diff| sums
__device__ int   g_tile_ticket[NTILES];
__device__ int   g_global_ticket;

__device__ __forceinline__ void edge_step2(float ax, float ay, float abx, float aby,
                                           float invdd, float px, float py,
                                           float& d2min, bool& pos, bool& neg) {
    float apx = px - ax;
    float apy = py - ay;
    float cross = abx * apy - aby * apx;
    pos = pos && (cross >= 0.0f);
    neg = neg && (cross <= 0.0f);
    float t = (apx * abx + apy * aby) * invdd;
    t = fminf(fmaxf(t, 0.0f), 1.0f);
    float ex = apx - t * abx;
    float ey = apy - t * aby;
    float d2 = ex * ex + ey * ey;
    d2min = fminf(d2min, d2);
}

// grid: (TILES_X, TILES_Y, NGROUP), block: (16,16)
__global__ void __launch_bounds__(TPB)
fused_sil_kernel(const float* __restrict__ verts,
                 const float* __restrict__ gt,
                 const int*   __restrict__ faces,
                 float* __restrict__ out) {
    // compacted face data: [eA, eB, eC, eD] per face
    __shared__ float4 s_f[FACES_PER_G * 4];
    __shared__ float  s_red[TPB];
    __shared__ int    s_wcnt[8];
    __shared__ int    s_n;
    __shared__ int    s_flag;

    int tid  = threadIdx.y * 16 + threadIdx.x;
    int wid  = tid >> 5;
    int lane = tid & 31;

    int gx   = blockIdx.x * TILE_W;
    int gy   = blockIdx.y * TILE_H;
    int grp  = blockIdx.z;
    int tile = blockIdx.y * TILES_X + blockIdx.x;

    // tile pixel-center bounds
    float tx0 = (float)gx + 0.5f;
    float tx1 = (float)gx + (float)(TILE_W - 1) + 0.5f;
    float ty0 = (float)gy + 0.5f;
    float ty1 = (float)gy + (float)(TILE_H - 1) + 0.5f;

    // ---- per-CTA face precompute (registers) + cull ----
    bool pass = false;
    float4 eA, eB, eC, eD;
    if (tid < FACES_PER_G) {
        int f = grp * FACES_PER_G + tid;
        float pxv[3], pyv[3];
        float tz = 0.0f;
#pragma unroll
        for (int k = 0; k < 3; k++) {
            int vi = faces[f * 3 + k];
            float x = verts[vi * 3 + 0];
            float y = verts[vi * 3 + 1];
            float z = verts[vi * 3 + 2];
            float vx = -x, vy = -y, vz = z;      // R = diag(-1,-1,1)
            tz += vz;
            float zc = fmaxf(vz, 1e-6f);
            pxv[k] = (F_LEN_F * vx / zc + C_PP_F) / CAM_F * (float)W_IMG;
            pyv[k] = (F_LEN_F * vy / zc + C_PP_F) / CAM_F * (float)H_IMG;
        }
        tz *= (1.0f / 3.0f);

        float ab0x = pxv[1] - pxv[0], ab0y = pyv[1] - pyv[0];
        float ab1x = pxv[2] - pxv[1], ab1y = pyv[2] - pyv[1];
        float ab2x = pxv[0] - pxv[2], ab2y = pyv[0] - pyv[2];
        float inv0 = 1.0f / (ab0x * ab0x + ab0y * ab0y + 1e-12f);
        float inv1 = 1.0f / (ab1x * ab1x + ab1y * ab1y + 1e-12f);
        float inv2 = 1.0f / (ab2x * ab2x + ab2y * ab2y + 1e-12f);

        eA = make_float4(pxv[0], pyv[0], ab0x, ab0y);
        eB = make_float4(pxv[1], pyv[1], ab1x, ab1y);
        eC = make_float4(pxv[2], pyv[2], ab2x, ab2y);
        eD = make_float4(inv0, inv1, inv2, tz);

        if (tz > 1e-6f) {
            float xmn = fminf(pxv[0], fminf(pxv[1], pxv[2])) - MARGIN_F;
            float xmx = fmaxf(pxv[0], fmaxf(pxv[1], pxv[2])) + MARGIN_F;
            float ymn = fminf(pyv[0], fminf(pyv[1], pyv[2])) - MARGIN_F;
            float ymx = fmaxf(pyv[0], fmaxf(pyv[1], pyv[2])) + MARGIN_F;
            pass = (xmn <= tx1) && (xmx >= tx0) && (ymn <= ty1) && (ymx >= ty0);
        }
    }

    // ---- deterministic ordered compaction of face DATA into smem ----
    unsigned mask = __ballot_sync(0xffffffffu, pass);
    if (lane == 0) s_wcnt[wid] = __popc(mask);
    __syncthreads();
    int woff = 0;
#pragma unroll
    for (int w = 0; w < 8; w++)
        if (w < wid) woff += s_wcnt[w];
    if (pass) {
        int pos = woff + __popc(mask & ((1u << lane) - 1u));
        s_f[pos * 4 + 0] = eA;
        s_f[pos * 4 + 1] = eB;
        s_f[pos * 4 + 2] = eC;
        s_f[pos * 4 + 3] = eD;
    }
    if (tid == 0) {
        int tot = 0;
#pragma unroll
        for (int w = 0; w < 8; w++) tot += s_wcnt[w];
        s_n = tot;
    }
    __syncthreads();
    int nf = s_n;

    // ---- per-pixel loop over compacted faces (broadcast LDS) ----
    int xi = gx + threadIdx.x;
    int yi = gy + threadIdx.y;
    float px = (float)xi + 0.5f;
    float py = (float)yi + 0.5f;

    float acc = 0.0f;
    for (int i = 0; i < nf; i++) {
        float4 fA = s_f[i * 4 + 0];
        float4 fB = s_f[i * 4 + 1];
        float4 fC = s_f[i * 4 + 2];
        float4 fD = s_f[i * 4 + 3];

        float d2min = __int_as_float(0x7f800000);  // +inf
        bool pos = true, neg = true;
        edge_step2(fA.x, fA.y, fA.z, fA.w, fD.x, px, py, d2min, pos, neg);
        edge_step2(fB.x, fB.y, fB.z, fB.w, fD.y, px, py, d2min, pos, neg);
        edge_step2(fC.x, fC.y, fC.z, fC.w, fD.z, px, py, d2min, pos, neg);

        bool inside = pos || neg;
        if (inside || (d2min <= BLUR_F)) {
            float xarg = (inside ? d2min : -d2min) * (1.0f / SIGMA_F);
            acc -= log1pf(__expf(xarg));   // log1p(-sigmoid(-x/s)) = -softplus
        }
    }

    // publish this group's partial (L2, coalesced per tile/group row)
    __stcg(&g_acc[(tile * NGROUP + grp) * TPB + tid], acc);
    __threadfence();

    // ---- per-tile ticket: last group CTA combines this tile ----
    if (tid == 0) {
        int old = atomicAdd(&g_tile_ticket[tile], 1);
        s_flag = (old == NGROUP - 1) ? 1 : 0;
    }
    __syncthreads();
    if (s_flag == 0) return;

    // combine groups for this tile
    float total = acc;  // own group's value already in register
#pragma unroll
    for (int g = 0; g < NGROUP; g++) {
        if (g == grp) continue;
        total += __ldcg(&g_acc[(tile * NGROUP + g) * TPB + tid]);
    }
    float alpha = 1.0f - __expf(total);

    float diff = 0.0f;
    if (xi < W_IMG) {   // yi always < H_IMG (240 = 15*16)
        int pix = yi * W_IMG + xi;
        out[1 + pix] = alpha;
        diff = fabsf(alpha - gt[pix]);
    }

    // block-reduce |diff|
    s_red[tid] = diff;
    __syncthreads();
#pragma unroll
    for (int off = 128; off > 0; off >>= 1) {
        if (tid < off) s_red[tid] += s_red[tid + off];
        __syncthreads();
    }
    if (tid == 0) {
        __stcg(&g_tilepart[tile], s_red[0]);
        __threadfence();
        int t = atomicAdd(&g_global_ticket, 1);
        s_flag = (t == NTILES - 1) ? 2 : 0;
    }
    __syncthreads();
    if (s_flag != 2) return;

    // ---- final: last tile sums 135 tile partials (fixed order) + resets ----
    float v = (tid < NTILES) ? __ldcg(&g_tilepart[tid]) : 0.0f;
    s_red[tid] = v;
    __syncthreads();
#pragma unroll
    for (int off = 128; off > 0; off >>= 1) {
        if (tid < off) s_red[tid] += s_red[tid + off];
        __syncthreads();
    }
    if (tid == 0) out[0] = s_red[0] * (1.0f / (float)NPIX);

    // reset tickets for next graph replay
    if (tid < NTILES) g_tile_ticket[tid] = 0;
    if (tid == 0) g_global_ticket = 0;
}

extern "C" void kernel_launch(void* const* d_in, const int* in_sizes, int n_in,
                              void* d_out, int out_size) {
    const float* verts = (const float*)d_in[0];
    const float* gt    = (const float*)d_in[1];
    const int*   faces = (const int*)d_in[2];
    float* out = (float*)d_out;

    dim3 grid(TILES_X, TILES_Y, NGROUP);
    dim3 block(16, 16);
    fused_sil_kernel<<<grid, block>>>(verts, gt, faces, out);
}

// round 7
// speedup vs baseline: 12.1087x; 1.3071x over previous
#include <cuda_runtime.h>
#include <cuda_bf16.h>
#include <cstdint>

// Problem constants (from reference)
#define H_IMG 240
#define W_IMG 135
#define NPIX  (H_IMG * W_IMG)   // 32400
#define NV    600
#define NF    1000
#define SIGMA_F 1e-4f
#define BLUR_F  9.210240366975850e-4f   // log(1/1e-4 - 1) * 1e-4
#define MARGIN_F 0.032f                 // > sqrt(BLUR_F) = 0.030348
#define F_LEN_F 1000.0f
#define C_PP_F  512.0f
#define CAM_F   1024.0f

#define TILE_W 16
#define TILE_H 16
#define TILES_X 9     // ceil(135/16)
#define TILES_Y 15    // 240/16
#define NTILES  (TILES_X * TILES_Y)   // 135
#define NGROUP  10
#define FACES_PER_G (NF / NGROUP)     // 100
#define TPB 256

// Once acc <= DONE_THRESH for all lanes, every remaining face term is <= 0,
// so the full-group partial is <= DONE_THRESH, hence total <= DONE_THRESH and
// alpha == 1.0f bit-exactly (exp(-100) < 2^-24) — same as the reference.
#define DONE_THRESH (-100.0f)
// Uniform sentinel published on early exit: makes the published value
// independent of the exact exit iteration. total <= -1e30 -> alpha = 1.0f.
#define SENTINEL    (-1e30f)

// Cross-CTA communication (device globals; zero-init at load, reset by kernel)
__device__ float g_acc[NTILES * NGROUP * TPB];  // per (tile, group, thread) partial
__device__ float g_tilepart[NTILES];            // per-tile |diff| sums
__device__ int   g_tile_ticket[NTILES];
__device__ int   g_global_ticket;

__device__ __forceinline__ void edge_step2(float ax, float ay, float abx, float aby,
                                           float invdd, float px, float py,
                                           float& d2min, bool& pos, bool& neg) {
    float apx = px - ax;
    float apy = py - ay;
    float cross = abx * apy - aby * apx;
    pos = pos && (cross >= 0.0f);
    neg = neg && (cross <= 0.0f);
    float t = (apx * abx + apy * aby) * invdd;
    t = fminf(fmaxf(t, 0.0f), 1.0f);
    float ex = apx - t * abx;
    float ey = apy - t * aby;
    float d2 = ex * ex + ey * ey;
    d2min = fminf(d2min, d2);
}

// grid: (TILES_X, TILES_Y, NGROUP), block: (16,16)
__global__ void __launch_bounds__(TPB)
fused_sil_kernel(const float* __restrict__ verts,
                 const float* __restrict__ gt,
                 const int*   __restrict__ faces,
                 float* __restrict__ out) {
    // compacted face data: [eA, eB, eC, eD] per face
    __shared__ float4 s_f[FACES_PER_G * 4];
    __shared__ float  s_red[TPB];
    __shared__ int    s_wcnt[8];
    __shared__ int    s_n;
    __shared__ int    s_flag;

    int tid  = threadIdx.y * 16 + threadIdx.x;
    int wid  = tid >> 5;
    int lane = tid & 31;

    int gx   = blockIdx.x * TILE_W;
    int gy   = blockIdx.y * TILE_H;
    int grp  = blockIdx.z;
    int tile = blockIdx.y * TILES_X + blockIdx.x;

    // tile pixel-center bounds
    float tx0 = (float)gx + 0.5f;
    float tx1 = (float)gx + (float)(TILE_W - 1) + 0.5f;
    float ty0 = (float)gy + 0.5f;
    float ty1 = (float)gy + (float)(TILE_H - 1) + 0.5f;

    // ---- per-CTA face precompute (registers) + cull ----
    bool pass = false;
    float4 eA, eB, eC, eD;
    if (tid < FACES_PER_G) {
        int f = grp * FACES_PER_G + tid;
        float pxv[3], pyv[3];
        float tz = 0.0f;
#pragma unroll
        for (int k = 0; k < 3; k++) {
            int vi = faces[f * 3 + k];
            float x = verts[vi * 3 + 0];
            float y = verts[vi * 3 + 1];
            float z = verts[vi * 3 + 2];
            float vx = -x, vy = -y, vz = z;      // R = diag(-1,-1,1)
            tz += vz;
            float zc = fmaxf(vz, 1e-6f);
            pxv[k] = (F_LEN_F * vx / zc + C_PP_F) / CAM_F * (float)W_IMG;
            pyv[k] = (F_LEN_F * vy / zc + C_PP_F) / CAM_F * (float)H_IMG;
        }
        tz *= (1.0f / 3.0f);

        float ab0x = pxv[1] - pxv[0], ab0y = pyv[1] - pyv[0];
        float ab1x = pxv[2] - pxv[1], ab1y = pyv[2] - pyv[1];
        float ab2x = pxv[0] - pxv[2], ab2y = pyv[0] - pyv[2];
        float inv0 = 1.0f / (ab0x * ab0x + ab0y * ab0y + 1e-12f);
        float inv1 = 1.0f / (ab1x * ab1x + ab1y * ab1y + 1e-12f);
        float inv2 = 1.0f / (ab2x * ab2x + ab2y * ab2y + 1e-12f);

        eA = make_float4(pxv[0], pyv[0], ab0x, ab0y);
        eB = make_float4(pxv[1], pyv[1], ab1x, ab1y);
        eC = make_float4(pxv[2], pyv[2], ab2x, ab2y);
        eD = make_float4(inv0, inv1, inv2, tz);

        if (tz > 1e-6f) {
            float xmn = fminf(pxv[0], fminf(pxv[1], pxv[2])) - MARGIN_F;
            float xmx = fmaxf(pxv[0], fmaxf(pxv[1], pxv[2])) + MARGIN_F;
            float ymn = fminf(pyv[0], fminf(pyv[1], pyv[2])) - MARGIN_F;
            float ymx = fmaxf(pyv[0], fmaxf(pyv[1], pyv[2])) + MARGIN_F;
            pass = (xmn <= tx1) && (xmx >= tx0) && (ymn <= ty1) && (ymx >= ty0);
        }
    }

    // ---- deterministic ordered compaction of face DATA into smem ----
    unsigned mask = __ballot_sync(0xffffffffu, pass);
    if (lane == 0) s_wcnt[wid] = __popc(mask);
    __syncthreads();
    int woff = 0;
#pragma unroll
    for (int w = 0; w < 8; w++)
        if (w < wid) woff += s_wcnt[w];
    if (pass) {
        int pos = woff + __popc(mask & ((1u << lane) - 1u));
        s_f[pos * 4 + 0] = eA;
        s_f[pos * 4 + 1] = eB;
        s_f[pos * 4 + 2] = eC;
        s_f[pos * 4 + 3] = eD;
    }
    if (tid == 0) {
        int tot = 0;
#pragma unroll
        for (int w = 0; w < 8; w++) tot += s_wcnt[w];
        s_n = tot;
    }
    __syncthreads();
    int nf = s_n;

    // ---- per-pixel loop over compacted faces (broadcast LDS) ----
    int xi = gx + threadIdx.x;
    int yi = gy + threadIdx.y;
    float px = (float)xi + 0.5f;
    float py = (float)yi + 0.5f;

    float acc = 0.0f;
    for (int i = 0; i < nf; i++) {
        float4 fA = s_f[i * 4 + 0];
        float4 fB = s_f[i * 4 + 1];
        float4 fC = s_f[i * 4 + 2];
        float4 fD = s_f[i * 4 + 3];

        float d2min = __int_as_float(0x7f800000);  // +inf
        bool pos = true, neg = true;
        edge_step2(fA.x, fA.y, fA.z, fA.w, fD.x, px, py, d2min, pos, neg);
        edge_step2(fB.x, fB.y, fB.z, fB.w, fD.y, px, py, d2min, pos, neg);
        edge_step2(fC.x, fC.y, fC.z, fC.w, fD.z, px, py, d2min, pos, neg);

        bool inside = pos || neg;
        if (inside || (d2min <= BLUR_F)) {
            // EXACT R4 accumulation (log1p(-sigmoid(-x/s)) = -softplus)
            float xarg = (inside ? d2min : -d2min) * (1.0f / SIGMA_F);
            acc -= log1pf(__expf(xarg));
        }

        // Warp early exit: all 32 lanes already <= DONE_THRESH. Every
        // remaining term is <= 0, so the full partial would also be
        // <= DONE_THRESH; publish a uniform sentinel so the stored value is
        // independent of the exit iteration. Output bits are unchanged:
        // total <= -100 -> alpha == 1.0f exactly, same as the reference.
        if (__ballot_sync(0xffffffffu, acc > DONE_THRESH) == 0u) {
            acc = SENTINEL;
            break;
        }
    }

    // publish this group's partial (L2, coalesced per tile/group row)
    __stcg(&g_acc[(tile * NGROUP + grp) * TPB + tid], acc);
    __threadfence();

    // ---- per-tile ticket: last group CTA combines this tile ----
    if (tid == 0) {
        int old = atomicAdd(&g_tile_ticket[tile], 1);
        s_flag = (old == NGROUP - 1) ? 1 : 0;
    }
    __syncthreads();
    if (s_flag == 0) return;

    // combine groups for this tile — FIXED order (deterministic regardless of
    // which group's CTA performs the combine)
    float total = 0.0f;
#pragma unroll
    for (int g = 0; g < NGROUP; g++)
        total += __ldcg(&g_acc[(tile * NGROUP + g) * TPB + tid]);
    float alpha = (total < -87.0f) ? 1.0f : (1.0f - __expf(total));

    float diff = 0.0f;
    if (xi < W_IMG) {   // yi always < H_IMG (240 = 15*16)
        int pix = yi * W_IMG + xi;
        out[1 + pix] = alpha;
        diff = fabsf(alpha - gt[pix]);
    }

    // block-reduce |diff|
    s_red[tid] = diff;
    __syncthreads();
#pragma unroll
    for (int off = 128; off > 0; off >>= 1) {
        if (tid < off) s_red[tid] += s_red[tid + off];
        __syncthreads();
    }
    if (tid == 0) {
        __stcg(&g_tilepart[tile], s_red[0]);
        __threadfence();
        int t = atomicAdd(&g_global_ticket, 1);
        s_flag = (t == NTILES - 1) ? 2 : 0;
    }
    __syncthreads();
    if (s_flag != 2) return;

    // ---- final: last tile sums 135 tile partials (fixed order) + resets ----
    float v = (tid < NTILES) ? __ldcg(&g_tilepart[tid]) : 0.0f;
    s_red[tid] = v;
    __syncthreads();
#pragma unroll
    for (int off = 128; off > 0; off >>= 1) {
        if (tid < off) s_red[tid] += s_red[tid + off];
        __syncthreads();
    }
    if (tid == 0) out[0] = s_red[0] * (1.0f / (float)NPIX);

    // reset tickets for next graph replay
    if (tid < NTILES) g_tile_ticket[tid] = 0;
    if (tid == 0) g_global_ticket = 0;
}

extern "C" void kernel_launch(void* const* d_in, const int* in_sizes, int n_in,
                              void* d_out, int out_size) {
    const float* verts = (const float*)d_in[0];
    const float* gt    = (const float*)d_in[1];
    const int*   faces = (const int*)d_in[2];
    float* out = (float*)d_out;

    dim3 grid(TILES_X, TILES_Y, NGROUP);
    dim3 block(16, 16);
    fused_sil_kernel<<<grid, block>>>(verts, gt, faces, out);
}

// round 9
// speedup vs baseline: 12.2586x; 1.0124x over previous
#include <cuda_runtime.h>
#include <cuda_bf16.h>
#include <cstdint>

// Problem constants (from reference)
#define H_IMG 240
#define W_IMG 135
#define NPIX  (H_IMG * W_IMG)   // 32400
#define NV    600
#define NF    1000
#define SIGMA_F 1e-4f
#define BLUR_F  9.210240366975850e-4f   // log(1/1e-4 - 1) * 1e-4
#define MARGIN_F 0.032f                 // > sqrt(BLUR_F) = 0.030348
#define F_LEN_F 1000.0f
#define C_PP_F  512.0f
#define CAM_F   1024.0f

#define TILE_W 16
#define TILE_H 16
#define TILES_X 9     // ceil(135/16)
#define TILES_Y 15    // 240/16
#define NTILES  (TILES_X * TILES_Y)   // 135
#define NGROUP  8                      // 135*8 = 1080 CTAs -> single wave @ 8 CTA/SM
#define FACES_PER_G (NF / NGROUP)      // 125
#define TPB 256

// Once acc <= DONE_THRESH for all lanes, every remaining face term is <= 0,
// so the full-group partial is <= DONE_THRESH, hence total <= DONE_THRESH and
// alpha == 1.0f bit-exactly — same as the reference.
#define DONE_THRESH (-100.0f)
#define SENTINEL    (-1e30f)

// Cross-CTA communication (device globals; zero-init at load, reset by kernel)
__device__ float g_acc[NTILES * NGROUP * TPB];  // per (tile, group, thread) partial
__device__ float g_tilepart[NTILES];            // per-tile |diff| sums
__device__ int   g_tile_ticket[NTILES];
__device__ int   g_global_ticket;

// grid: (TILES_X, TILES_Y, NGROUP), block: (16,16)
__global__ void __launch_bounds__(TPB, 8)
fused_sil_kernel(const float* __restrict__ verts,
                 const float* __restrict__ gt,
                 const int*   __restrict__ faces,
                 float* __restrict__ out) {
    // compacted face data, 5 float4 per face:
    //  [0] a0x,a0y,ab0x,ab0y   [1] a1...,ab1...   [2] a2...,ab2...
    //  [3] thr0,thr1,thr2 (BLUR*dd_k)            [4] inv0,inv1,inv2
    __shared__ float4 s_f[FACES_PER_G * 5];
    __shared__ float  s_red[TPB];
    __shared__ int    s_wcnt[8];
    __shared__ int    s_n;
    __shared__ int    s_flag;

    int tid  = threadIdx.y * 16 + threadIdx.x;
    int wid  = tid >> 5;
    int lane = tid & 31;

    int gx   = blockIdx.x * TILE_W;
    int gy   = blockIdx.y * TILE_H;
    int grp  = blockIdx.z;
    int tile = blockIdx.y * TILES_X + blockIdx.x;

    // tile pixel-center bounds
    float tx0 = (float)gx + 0.5f;
    float tx1 = (float)gx + (float)(TILE_W - 1) + 0.5f;
    float ty0 = (float)gy + 0.5f;
    float ty1 = (float)gy + (float)(TILE_H - 1) + 0.5f;

    // ---- per-CTA face precompute (registers) + cull ----
    bool pass = false;
    float4 eA, eB, eC, eD, eE;
    if (tid < FACES_PER_G) {
        int f = grp * FACES_PER_G + tid;
        float pxv[3], pyv[3];
        float tz = 0.0f;
#pragma unroll
        for (int k = 0; k < 3; k++) {
            int vi = faces[f * 3 + k];
            float x = verts[vi * 3 + 0];
            float y = verts[vi * 3 + 1];
            float z = verts[vi * 3 + 2];
            float vx = -x, vy = -y, vz = z;      // R = diag(-1,-1,1)
            tz += vz;
            float zc = fmaxf(vz, 1e-6f);
            pxv[k] = (F_LEN_F * vx / zc + C_PP_F) / CAM_F * (float)W_IMG;
            pyv[k] = (F_LEN_F * vy / zc + C_PP_F) / CAM_F * (float)H_IMG;
        }
        tz *= (1.0f / 3.0f);

        float ab0x = pxv[1] - pxv[0], ab0y = pyv[1] - pyv[0];
        float ab1x = pxv[2] - pxv[1], ab1y = pyv[2] - pyv[1];
        float ab2x = pxv[0] - pxv[2], ab2y = pyv[0] - pyv[2];
        float dd0 = ab0x * ab0x + ab0y * ab0y + 1e-12f;
        float dd1 = ab1x * ab1x + ab1y * ab1y + 1e-12f;
        float dd2 = ab2x * ab2x + ab2y * ab2y + 1e-12f;

        eA = make_float4(pxv[0], pyv[0], ab0x, ab0y);
        eB = make_float4(pxv[1], pyv[1], ab1x, ab1y);
        eC = make_float4(pxv[2], pyv[2], ab2x, ab2y);
        eD = make_float4(BLUR_F * dd0, BLUR_F * dd1, BLUR_F * dd2, 0.0f);
        eE = make_float4(1.0f / dd0, 1.0f / dd1, 1.0f / dd2, 0.0f);

        if (tz > 1e-6f) {
            float xmn = fminf(pxv[0], fminf(pxv[1], pxv[2])) - MARGIN_F;
            float xmx = fmaxf(pxv[0], fmaxf(pxv[1], pxv[2])) + MARGIN_F;
            float ymn = fminf(pyv[0], fminf(pyv[1], pyv[2])) - MARGIN_F;
            float ymx = fmaxf(pyv[0], fmaxf(pyv[1], pyv[2])) + MARGIN_F;
            pass = (xmn <= tx1) && (xmx >= tx0) && (ymn <= ty1) && (ymx >= ty0);
        }
    }

    // ---- deterministic ordered compaction of face DATA into smem ----
    unsigned mask = __ballot_sync(0xffffffffu, pass);
    if (lane == 0) s_wcnt[wid] = __popc(mask);
    __syncthreads();
    int woff = 0;
#pragma unroll
    for (int w = 0; w < 8; w++)
        if (w < wid) woff += s_wcnt[w];
    if (pass) {
        int pos = woff + __popc(mask & ((1u << lane) - 1u));
        s_f[pos * 5 + 0] = eA;
        s_f[pos * 5 + 1] = eB;
        s_f[pos * 5 + 2] = eC;
        s_f[pos * 5 + 3] = eD;
        s_f[pos * 5 + 4] = eE;
    }
    if (tid == 0) {
        int tot = 0;
#pragma unroll
        for (int w = 0; w < 8; w++) tot += s_wcnt[w];
        s_n = tot;
    }
    __syncthreads();
    int nf = s_n;

    // ---- per-pixel loop over compacted faces (broadcast LDS) ----
    int xi = gx + threadIdx.x;
    int yi = gy + threadIdx.y;
    float px = (float)xi + 0.5f;
    float py = (float)yi + 0.5f;

    float acc = 0.0f;
    for (int i = 0; i < nf; i++) {
        float4 fA = s_f[i * 5 + 0];
        float4 fB = s_f[i * 5 + 1];
        float4 fC = s_f[i * 5 + 2];
        float4 fD = s_f[i * 5 + 3];

        float ap0x = px - fA.x, ap0y = py - fA.y;
        float ap1x = px - fB.x, ap1y = py - fB.y;
        float ap2x = px - fC.x, ap2y = py - fC.y;

        float c0 = fA.z * ap0y - fA.w * ap0x;
        float c1 = fB.z * ap1y - fB.w * ap1x;
        float c2 = fC.z * ap2y - fC.w * ap2x;

        float cmn = fminf(fminf(c0, c1), c2);
        float cmx = fmaxf(fmaxf(c0, c1), c2);
        bool inside = (cmn >= 0.0f) || (cmx <= 0.0f);

        // conservative "far" test: line-dist^2 > BLUR for every edge
        //   cross^2 > BLUR*dd  =>  cross^2/|ab|^2 > BLUR  => seg-dist^2 > BLUR
        bool far = (c0 * c0 > fD.x) && (c1 * c1 > fD.y) && (c2 * c2 > fD.z);

        if (inside || !far) {
            float4 fE = s_f[i * 5 + 4];

            float t0 = fminf(fmaxf((ap0x * fA.z + ap0y * fA.w) * fE.x, 0.0f), 1.0f);
            float e0x = ap0x - t0 * fA.z, e0y = ap0y - t0 * fA.w;
            float d0 = e0x * e0x + e0y * e0y;

            float t1 = fminf(fmaxf((ap1x * fB.z + ap1y * fB.w) * fE.y, 0.0f), 1.0f);
            float e1x = ap1x - t1 * fB.z, e1y = ap1y - t1 * fB.w;
            float d1 = e1x * e1x + e1y * e1y;

            float t2 = fminf(fmaxf((ap2x * fC.z + ap2y * fC.w) * fE.z, 0.0f), 1.0f);
            float e2x = ap2x - t2 * fC.z, e2y = ap2y - t2 * fC.w;
            float d2 = e2x * e2x + e2y * e2y;

            float d2min = fminf(d0, fminf(d1, d2));

            if (inside || (d2min <= BLUR_F)) {
                float xarg = (inside ? d2min : -d2min) * (1.0f / SIGMA_F);
                acc -= log1pf(__expf(xarg));   // -softplus, exact R4/R7 form
            }
        }

        // Warp early exit (output-invisible, see R7): publish uniform sentinel.
        if (__ballot_sync(0xffffffffu, acc > DONE_THRESH) == 0u) {
            acc = SENTINEL;
            break;
        }
    }

    // publish this group's partial (release: store -> fence -> ticket RMW)
    __stcg(&g_acc[(tile * NGROUP + grp) * TPB + tid], acc);
    __threadfence();

    // ---- per-tile ticket: last group CTA combines this tile ----
    if (tid == 0) {
        int old = atomicAdd(&g_tile_ticket[tile], 1);
        s_flag = (old == NGROUP - 1) ? 1 : 0;
        __threadfence();   // ACQUIRE side: pairs with writers' release fences;
                           // orders the combine loads below after the observed
                           // ticket value (propagated to the block by the
                           // following __syncthreads)
    }
    __syncthreads();
    if (s_flag == 0) return;

    // combine groups for this tile — FIXED order (deterministic)
    float total = 0.0f;
#pragma unroll
    for (int g = 0; g < NGROUP; g++)
        total += __ldcg(&g_acc[(tile * NGROUP + g) * TPB + tid]);
    float alpha = (total < -87.0f) ? 1.0f : (1.0f - __expf(total));

    float diff = 0.0f;
    if (xi < W_IMG) {   // yi always < H_IMG (240 = 15*16)
        int pix = yi * W_IMG + xi;
        out[1 + pix] = alpha;
        diff = fabsf(alpha - gt[pix]);
    }

    // block-reduce |diff|
    s_red[tid] = diff;
    __syncthreads();
#pragma unroll
    for (int off = 128; off > 0; off >>= 1) {
        if (tid < off) s_red[tid] += s_red[tid + off];
        __syncthreads();
    }
    if (tid == 0) {
        __stcg(&g_tilepart[tile], s_red[0]);
        __threadfence();   // release for g_tilepart
        int t = atomicAdd(&g_global_ticket, 1);
        s_flag = (t == NTILES - 1) ? 2 : 0;
        __threadfence();   // ACQUIRE side for the final-stage loads
    }
    __syncthreads();
    if (s_flag != 2) return;

    // ---- final: last tile sums 135 tile partials (fixed order) + resets ----
    float v = (tid < NTILES) ? __ldcg(&g_tilepart[tid]) : 0.0f;
    s_red[tid] = v;
    __syncthreads();
#pragma unroll
    for (int off = 128; off > 0; off >>= 1) {
        if (tid < off) s_red[tid] += s_red[tid + off];
        __syncthreads();
    }
    if (tid == 0) out[0] = s_red[0] * (1.0f / (float)NPIX);

    // reset tickets for next graph replay
    if (tid < NTILES) g_tile_ticket[tid] = 0;
    if (tid == 0) g_global_ticket = 0;
}

extern "C" void kernel_launch(void* const* d_in, const int* in_sizes, int n_in,
                              void* d_out, int out_size) {
    const float* verts = (const float*)d_in[0];
    const float* gt    = (const float*)d_in[1];
    const int*   faces = (const int*)d_in[2];
    float* out = (float*)d_out;

    dim3 grid(TILES_X, TILES_Y, NGROUP);
    dim3 block(16, 16);
    fused_sil_kernel<<<grid, block>>>(verts, gt, faces, out);
}

// round 10
// speedup vs baseline: 13.6061x; 1.1099x over previous
#include <cuda_runtime.h>
#include <cuda_bf16.h>
#include <cstdint>

// Problem constants (from reference)
#define H_IMG 240
#define W_IMG 135
#define NPIX  (H_IMG * W_IMG)   // 32400
#define NV    600
#define NF    1000
#define SIGMA_F 1e-4f
#define BLUR_F  9.210240366975850e-4f   // log(1/1e-4 - 1) * 1e-4
#define MARGIN_F 0.032f                 // > sqrt(BLUR_F) = 0.030348
#define F_LEN_F 1000.0f
#define C_PP_F  512.0f
#define CAM_F   1024.0f

// Conservative near-band threshold on NORMALIZED line distance:
// sqrt(BLUR) = 0.0303484; add margin >> fp32 abs error of the L ffma chain
// (~6e-5 at coords ~240). Pairs in the gray zone take the exact slow path.
#define SQRT_BLUR_SAFE 0.0306f

#define TILE_W 16
#define TILE_H 16
#define TILES_X 9     // ceil(135/16)
#define TILES_Y 15    // 240/16
#define NTILES  (TILES_X * TILES_Y)   // 135
#define NGROUP  8                      // 135*8 = 1080 CTAs -> single wave @ 8 CTA/SM
#define FACES_PER_G (NF / NGROUP)      // 125
#define TPB 256

// Once acc <= DONE_THRESH for all lanes, every remaining face term is <= 0,
// so the full-group partial is <= DONE_THRESH, hence total <= DONE_THRESH and
// alpha == 1.0f bit-exactly — same as the reference.
#define DONE_THRESH (-100.0f)
#define SENTINEL    (-1e30f)

// Cross-CTA communication (device globals; zero-init at load, reset by kernel)
__device__ float g_acc[NTILES * NGROUP * TPB];  // per (tile, group, thread) partial
__device__ float g_tilepart[NTILES];            // per-tile |diff| sums
__device__ int   g_tile_ticket[NTILES];
__device__ int   g_global_ticket;

// grid: (TILES_X, TILES_Y, NGROUP), block: (16,16)
__global__ void __launch_bounds__(TPB, 8)
fused_sil_kernel(const float* __restrict__ verts,
                 const float* __restrict__ gt,
                 const int*   __restrict__ faces,
                 float* __restrict__ out) {
    // fast-path data, 3 float4/face: (nkx, nky, ck, inv_k) per edge k
    //   L_k = nkx*px + nky*py + ck  (normalized line distance, sign = cross sign)
    // slow-path data, 3 float4/face: (akx, aky, ab_kx, ab_ky) per edge k
    __shared__ float4 s_fast[FACES_PER_G * 3];
    __shared__ float4 s_slow[FACES_PER_G * 3];
    __shared__ float  s_red[TPB];
    __shared__ int    s_wcnt[8];
    __shared__ int    s_n;
    __shared__ int    s_flag;

    int tid  = threadIdx.y * 16 + threadIdx.x;
    int wid  = tid >> 5;
    int lane = tid & 31;

    int gx   = blockIdx.x * TILE_W;
    int gy   = blockIdx.y * TILE_H;
    int grp  = blockIdx.z;
    int tile = blockIdx.y * TILES_X + blockIdx.x;

    // tile pixel-center bounds
    float tx0 = (float)gx + 0.5f;
    float tx1 = (float)gx + (float)(TILE_W - 1) + 0.5f;
    float ty0 = (float)gy + 0.5f;
    float ty1 = (float)gy + (float)(TILE_H - 1) + 0.5f;

    // ---- per-CTA face precompute (registers) + cull ----
    bool pass = false;
    float4 eF0, eF1, eF2, eS0, eS1, eS2;
    if (tid < FACES_PER_G) {
        int f = grp * FACES_PER_G + tid;
        float pxv[3], pyv[3];
        float tz = 0.0f;
#pragma unroll
        for (int k = 0; k < 3; k++) {
            int vi = faces[f * 3 + k];
            float x = verts[vi * 3 + 0];
            float y = verts[vi * 3 + 1];
            float z = verts[vi * 3 + 2];
            float vx = -x, vy = -y, vz = z;      // R = diag(-1,-1,1)
            tz += vz;
            float zc = fmaxf(vz, 1e-6f);
            pxv[k] = (F_LEN_F * vx / zc + C_PP_F) / CAM_F * (float)W_IMG;
            pyv[k] = (F_LEN_F * vy / zc + C_PP_F) / CAM_F * (float)H_IMG;
        }
        tz *= (1.0f / 3.0f);

        float4 fast[3], slow[3];
#pragma unroll
        for (int k = 0; k < 3; k++) {
            int k2 = (k + 1) % 3;
            float ax = pxv[k],  ay = pyv[k];
            float abx = pxv[k2] - ax, aby = pyv[k2] - ay;
            float dd  = abx * abx + aby * aby + 1e-12f;
            float inv = 1.0f / dd;
            float rlen = rsqrtf(dd);
            float nx = -aby * rlen;
            float ny =  abx * rlen;
            float c  = -(nx * ax + ny * ay);
            fast[k] = make_float4(nx, ny, c, inv);
            slow[k] = make_float4(ax, ay, abx, aby);
        }
        eF0 = fast[0]; eF1 = fast[1]; eF2 = fast[2];
        eS0 = slow[0]; eS1 = slow[1]; eS2 = slow[2];

        if (tz > 1e-6f) {
            float xmn = fminf(pxv[0], fminf(pxv[1], pxv[2])) - MARGIN_F;
            float xmx = fmaxf(pxv[0], fmaxf(pxv[1], pxv[2])) + MARGIN_F;
            float ymn = fminf(pyv[0], fminf(pyv[1], pyv[2])) - MARGIN_F;
            float ymx = fmaxf(pyv[0], fmaxf(pyv[1], pyv[2])) + MARGIN_F;
            pass = (xmn <= tx1) && (xmx >= tx0) && (ymn <= ty1) && (ymx >= ty0);
        }
    }

    // ---- deterministic ordered compaction of face DATA into smem ----
    unsigned mask = __ballot_sync(0xffffffffu, pass);
    if (lane == 0) s_wcnt[wid] = __popc(mask);
    __syncthreads();
    int woff = 0;
#pragma unroll
    for (int w = 0; w < 8; w++)
        if (w < wid) woff += s_wcnt[w];
    if (pass) {
        int pos = woff + __popc(mask & ((1u << lane) - 1u));
        s_fast[pos * 3 + 0] = eF0;
        s_fast[pos * 3 + 1] = eF1;
        s_fast[pos * 3 + 2] = eF2;
        s_slow[pos * 3 + 0] = eS0;
        s_slow[pos * 3 + 1] = eS1;
        s_slow[pos * 3 + 2] = eS2;
    }
    if (tid == 0) {
        int tot = 0;
#pragma unroll
        for (int w = 0; w < 8; w++) tot += s_wcnt[w];
        s_n = tot;
    }
    __syncthreads();
    int nf = s_n;

    // ---- per-pixel loop over compacted faces (broadcast LDS) ----
    int xi = gx + threadIdx.x;
    int yi = gy + threadIdx.y;
    float px = (float)xi + 0.5f;
    float py = (float)yi + 0.5f;

    float acc = 0.0f;
    for (int i = 0; i < nf; i++) {
        float4 f0 = s_fast[i * 3 + 0];
        float4 f1 = s_fast[i * 3 + 1];
        float4 f2 = s_fast[i * 3 + 2];

        // normalized signed line distances (sign == cross sign)
        float L0 = fmaf(f0.x, px, fmaf(f0.y, py, f0.z));
        float L1 = fmaf(f1.x, px, fmaf(f1.y, py, f1.z));
        float L2 = fmaf(f2.x, px, fmaf(f2.y, py, f2.z));

        float Lmn = fminf(L0, fminf(L1, L2));
        float Lmx = fmaxf(L0, fmaxf(L1, L2));
        bool inside = (Lmn >= 0.0f) || (Lmx <= 0.0f);

        // conservative near test: min line distance <= safe threshold.
        // seg-dist >= line-dist per edge, so min|L| > thr  =>  d2min > BLUR.
        float amn = fminf(fabsf(L0), fminf(fabsf(L1), fabsf(L2)));

        if (inside || (amn <= SQRT_BLUR_SAFE)) {
            // exact segment-distance path (R4 math, inv packed in f_k.w)
            float4 s0 = s_slow[i * 3 + 0];
            float4 s1 = s_slow[i * 3 + 1];
            float4 s2 = s_slow[i * 3 + 2];

            float ap0x = px - s0.x, ap0y = py - s0.y;
            float t0 = fminf(fmaxf((ap0x * s0.z + ap0y * s0.w) * f0.w, 0.0f), 1.0f);
            float e0x = ap0x - t0 * s0.z, e0y = ap0y - t0 * s0.w;
            float d0 = e0x * e0x + e0y * e0y;

            float ap1x = px - s1.x, ap1y = py - s1.y;
            float t1 = fminf(fmaxf((ap1x * s1.z + ap1y * s1.w) * f1.w, 0.0f), 1.0f);
            float e1x = ap1x - t1 * s1.z, e1y = ap1y - t1 * s1.w;
            float d1 = e1x * e1x + e1y * e1y;

            float ap2x = px - s2.x, ap2y = py - s2.y;
            float t2 = fminf(fmaxf((ap2x * s2.z + ap2y * s2.w) * f2.w, 0.0f), 1.0f);
            float e2x = ap2x - t2 * s2.z, e2y = ap2y - t2 * s2.w;
            float d2 = e2x * e2x + e2y * e2y;

            float d2min = fminf(d0, fminf(d1, d2));

            if (inside || (d2min <= BLUR_F)) {
                float xarg = (inside ? d2min : -d2min) * (1.0f / SIGMA_F);
                acc -= log1pf(__expf(xarg));   // -softplus, exact R4/R7 form
            }
        }

        // Warp early exit (output-invisible, see R7): publish uniform sentinel.
        if (__ballot_sync(0xffffffffu, acc > DONE_THRESH) == 0u) {
            acc = SENTINEL;
            break;
        }
    }

    // publish this group's partial (release: store -> fence -> ticket RMW)
    __stcg(&g_acc[(tile * NGROUP + grp) * TPB + tid], acc);
    __threadfence();

    // ---- per-tile ticket: last group CTA combines this tile ----
    if (tid == 0) {
        int old = atomicAdd(&g_tile_ticket[tile], 1);
        s_flag = (old == NGROUP - 1) ? 1 : 0;
        __threadfence();   // ACQUIRE side: pairs with writers' release fences
    }
    __syncthreads();
    if (s_flag == 0) return;

    // combine groups for this tile — FIXED order (deterministic)
    float total = 0.0f;
#pragma unroll
    for (int g = 0; g < NGROUP; g++)
        total += __ldcg(&g_acc[(tile * NGROUP + g) * TPB + tid]);
    float alpha = (total < -87.0f) ? 1.0f : (1.0f - __expf(total));

    float diff = 0.0f;
    if (xi < W_IMG) {   // yi always < H_IMG (240 = 15*16)
        int pix = yi * W_IMG + xi;
        out[1 + pix] = alpha;
        diff = fabsf(alpha - gt[pix]);
    }

    // block-reduce |diff|
    s_red[tid] = diff;
    __syncthreads();
#pragma unroll
    for (int off = 128; off > 0; off >>= 1) {
        if (tid < off) s_red[tid] += s_red[tid + off];
        __syncthreads();
    }
    if (tid == 0) {
        __stcg(&g_tilepart[tile], s_red[0]);
        __threadfence();   // release for g_tilepart
        int t = atomicAdd(&g_global_ticket, 1);
        s_flag = (t == NTILES - 1) ? 2 : 0;
        __threadfence();   // ACQUIRE side for the final-stage loads
    }
    __syncthreads();
    if (s_flag != 2) return;

    // ---- final: last tile sums 135 tile partials (fixed order) + resets ----
    float v = (tid < NTILES) ? __ldcg(&g_tilepart[tid]) : 0.0f;
    s_red[tid] = v;
    __syncthreads();
#pragma unroll
    for (int off = 128; off > 0; off >>= 1) {
        if (tid < off) s_red[tid] += s_red[tid + off];
        __syncthreads();
    }
    if (tid == 0) out[0] = s_red[0] * (1.0f / (float)NPIX);

    // reset tickets for next graph replay
    if (tid < NTILES) g_tile_ticket[tid] = 0;
    if (tid == 0) g_global_ticket = 0;
}

extern "C" void kernel_launch(void* const* d_in, const int* in_sizes, int n_in,
                              void* d_out, int out_size) {
    const float* verts = (const float*)d_in[0];
    const float* gt    = (const float*)d_in[1];
    const int*   faces = (const int*)d_in[2];
    float* out = (float*)d_out;

    dim3 grid(TILES_X, TILES_Y, NGROUP);
    dim3 block(16, 16);
    fused_sil_kernel<<<grid, block>>>(verts, gt, faces, out);
}